// round 8
// baseline (speedup 1.0000x reference)
#include <cuda_runtime.h>
#include <stdint.h>

#define Hh 256
#define Ww 256
#define Bb 16
#define CI 32
#define CO 32
#define Mm 4

// Binarized activations: 1 bit per input channel, one u32 per pixel (4 MB).
__device__ uint32_t g_xbits[Bb * Hh * Ww];
// Per (tap, cout): bitplanes m0,m1,m2 of p (count of non-negative W over m). .w unused.
__device__ uint4 g_masks[9 * CO];
// Per (border-class, cout): sum over VALID taps of (128 - 2P) + sum_m b[m][cout].
__device__ float g_bias[9 * CO];

// ---------------------------------------------------------------------------
// K0: weight prep. One block, 288 threads = (tap 0..8) x (cout 0..31).
// Phase 1: build bitplane masks + P per (tap,cout).
// Phase 2: build 9-class border bias table (reusing threads as (class,cout)).
// ---------------------------------------------------------------------------
__global__ void k0_prep(const float* __restrict__ W, const float* __restrict__ b) {
    __shared__ int sP[9 * CO];
    int tid = threadIdx.x;      // 0..287
    int t = tid >> 5;           // tap 0..8
    int o = tid & 31;           // cout

    uint32_t m0 = 0, m1 = 0, m2 = 0;
    int P = 0;
#pragma unroll 4
    for (int c = 0; c < CI; c++) {
        int p = 0;
#pragma unroll
        for (int m = 0; m < Mm; m++) {
            // W[m, ky, kx, c, o] with t = ky*3+kx
            float w = W[((m * 9 + t) * CI + c) * CO + o];
            p += (w >= 0.0f) ? 1 : 0;
        }
        m0 |= (uint32_t)(p & 1) << c;
        m1 |= (uint32_t)((p >> 1) & 1) << c;
        m2 |= (uint32_t)((p >> 2) & 1) << c;
        P += p;
    }
    g_masks[t * CO + o] = make_uint4(m0, m1, m2, 0u);
    sP[t * CO + o] = P;
    __syncthreads();

    // Phase 2: class = t (0..8): yc = class/3, xc = class%3
    int cl = t;
    int yc = cl / 3, xc = cl % 3;
    int acc = 0;
#pragma unroll
    for (int tt = 0; tt < 9; tt++) {
        int dy = tt / 3 - 1, dx = tt % 3 - 1;
        bool valid = !(dy < 0 && yc == 0) && !(dy > 0 && yc == 2) &&
                     !(dx < 0 && xc == 0) && !(dx > 0 && xc == 2);
        if (valid) acc += 128 - 2 * sP[tt * CO + o];
    }
    float bs = 0.0f;
#pragma unroll
    for (int m = 0; m < Mm; m++) bs += b[m * CO + o];
    g_bias[cl * CO + o] = (float)acc + bs;
}

// ---------------------------------------------------------------------------
// K1: binarize x. One warp handles 8 pixels; lane c reads channel c (fully
// coalesced 128B per warp), __ballot builds the 32-bit channel mask directly.
// ---------------------------------------------------------------------------
__global__ void __launch_bounds__(256) k1_binarize(const float* __restrict__ x) {
    int lane = threadIdx.x & 31;
    int warp = (blockIdx.x * blockDim.x + threadIdx.x) >> 5;
    int pix0 = warp * 8;
#pragma unroll
    for (int i = 0; i < 8; i++) {
        int pix = pix0 + i;
        float v = x[(size_t)pix * CI + lane];
        uint32_t bits = __ballot_sync(0xffffffffu, v >= 0.0f);
        if (lane == 0) g_xbits[pix] = bits;
    }
}

// ---------------------------------------------------------------------------
// K2: binary conv. Block = 256 threads covers a 128-pixel row strip of one
// (batch,row). Thread = (run of 8 pixels) x (pair of couts). Masks live in
// registers (54 regs), x-words in smem (3 rows x 130 words, zero-padded halo).
// ---------------------------------------------------------------------------
__global__ void __launch_bounds__(256) k2_conv(float* __restrict__ y) {
    __shared__ uint32_t sx[3][132];

    int tid = threadIdx.x;
    int x0 = blockIdx.x * 128;
    int yy = blockIdx.y;
    int bz = blockIdx.z;
    const uint32_t* xb = g_xbits + (size_t)bz * (Hh * Ww);

    // Stage 3 rows (y-1..y+1), cols x0-1..x0+128, zero outside the image.
    for (int i = tid; i < 3 * 130; i += 256) {
        int rr = i / 130, cc = i % 130;
        int gy = yy + rr - 1;
        int gx = x0 + cc - 1;
        uint32_t v = 0;
        if (gy >= 0 && gy < Hh && gx >= 0 && gx < Ww) v = xb[gy * Ww + gx];
        sx[rr][cc] = v;
    }
    __syncthreads();

    int g = tid & 15;       // cout pair index
    int r = tid >> 4;       // pixel run index (0..15)
    int pxb = r * 8;
    int co = g * 2;

    // Load this thread's 9 taps x 2 couts x 3 bitplane masks into registers.
    uint32_t mk[9][2][3];
#pragma unroll
    for (int t = 0; t < 9; t++) {
#pragma unroll
        for (int j = 0; j < 2; j++) {
            uint4 v = __ldg(&g_masks[t * CO + co + j]);
            mk[t][j][0] = v.x;
            mk[t][j][1] = v.y;
            mk[t][j][2] = v.z;
        }
    }

    int yc = (yy == 0) ? 0 : ((yy == Hh - 1) ? 2 : 1);
    float* yout = y + (size_t)(bz * Hh + yy) * Ww * CO;

#pragma unroll
    for (int px = 0; px < 8; px++) {
        int col = pxb + px;               // smem col of dx=-1 word
        uint32_t w[9];
#pragma unroll
        for (int rr2 = 0; rr2 < 3; rr2++)
#pragma unroll
            for (int dc = 0; dc < 3; dc++) w[rr2 * 3 + dc] = sx[rr2][col + dc];

        int T = 0;
#pragma unroll
        for (int t = 0; t < 9; t++) T += __popc(w[t]);

        int gx = x0 + col;
        int xc = (gx == 0) ? 0 : ((gx == Ww - 1) ? 2 : 1);
        int cl = yc * 3 + xc;

        float2 outv;
#pragma unroll
        for (int j = 0; j < 2; j++) {
            int A0 = 0, A1 = 0, A2 = 0;
#pragma unroll
            for (int t = 0; t < 9; t++) {
                A0 += __popc(w[t] & mk[t][j][0]);
                A1 += __popc(w[t] & mk[t][j][1]);
                A2 += __popc(w[t] & mk[t][j][2]);
            }
            int val = 4 * (A0 + 2 * A1 + 4 * A2) - 8 * T;
            float bias = __ldg(&g_bias[cl * CO + co + j]);
            ((float*)&outv)[j] = (float)val + bias;
        }
        *(float2*)(yout + (size_t)gx * CO + co) = outv;
    }
}

// ---------------------------------------------------------------------------
extern "C" void kernel_launch(void* const* d_in, const int* in_sizes, int n_in,
                              void* d_out, int out_size) {
    const float* x = (const float*)d_in[0];
    const float* W = (const float*)d_in[1];
    const float* b = (const float*)d_in[2];
    float* y = (float*)d_out;

    k0_prep<<<1, 288>>>(W, b);

    // 16*256*256 = 1,048,576 pixels; 64 pixels per 256-thread block.
    k1_binarize<<<16384, 256>>>(x);

    dim3 grid(Ww / 128, Hh, Bb);
    k2_conv<<<grid, 256>>>(y);
}

// round 9
// speedup vs baseline: 1.0075x; 1.0075x over previous
#include <cuda_runtime.h>
#include <stdint.h>

#define Hh 256
#define Ww 256
#define Bb 16
#define CI 32
#define CO 32
#define Mm 4

// Binarized activations: 1 bit per input channel, one u32 per pixel (4 MB).
__device__ uint32_t g_xbits[Bb * Hh * Ww];
// Per (tap, cout): bitplanes m0,m1,m2 of p (count of non-negative W over m). .w unused.
__device__ uint4 g_masks[9 * CO];
// Per (border-class, cout): sum over VALID taps of (128 - 2P) + sum_m b[m][cout].
__device__ float g_bias[9 * CO];

// ---------------------------------------------------------------------------
// K0: weight prep. One block, 288 threads = (tap 0..8) x (cout 0..31).
// Phase 1: build bitplane masks + P per (tap,cout).
// Phase 2: build 9-class border bias table (reusing threads as (class,cout)).
// ---------------------------------------------------------------------------
__global__ void k0_prep(const float* __restrict__ W, const float* __restrict__ b) {
    __shared__ int sP[9 * CO];
    int tid = threadIdx.x;      // 0..287
    int t = tid >> 5;           // tap 0..8
    int o = tid & 31;           // cout

    uint32_t m0 = 0, m1 = 0, m2 = 0;
    int P = 0;
#pragma unroll 4
    for (int c = 0; c < CI; c++) {
        int p = 0;
#pragma unroll
        for (int m = 0; m < Mm; m++) {
            // W[m, ky, kx, c, o] with t = ky*3+kx
            float w = W[((m * 9 + t) * CI + c) * CO + o];
            p += (w >= 0.0f) ? 1 : 0;
        }
        m0 |= (uint32_t)(p & 1) << c;
        m1 |= (uint32_t)((p >> 1) & 1) << c;
        m2 |= (uint32_t)((p >> 2) & 1) << c;
        P += p;
    }
    g_masks[t * CO + o] = make_uint4(m0, m1, m2, 0u);
    sP[t * CO + o] = P;
    __syncthreads();

    // Phase 2: class = t (0..8): yc = class/3, xc = class%3
    int cl = t;
    int yc = cl / 3, xc = cl % 3;
    int acc = 0;
#pragma unroll
    for (int tt = 0; tt < 9; tt++) {
        int dy = tt / 3 - 1, dx = tt % 3 - 1;
        bool valid = !(dy < 0 && yc == 0) && !(dy > 0 && yc == 2) &&
                     !(dx < 0 && xc == 0) && !(dx > 0 && xc == 2);
        if (valid) acc += 128 - 2 * sP[tt * CO + o];
    }
    float bs = 0.0f;
#pragma unroll
    for (int m = 0; m < Mm; m++) bs += b[m * CO + o];
    g_bias[cl * CO + o] = (float)acc + bs;
}

// ---------------------------------------------------------------------------
// K1: binarize x. One warp handles 8 pixels; lane c reads channel c (fully
// coalesced 128B per warp), __ballot builds the 32-bit channel mask directly.
// ---------------------------------------------------------------------------
__global__ void __launch_bounds__(256) k1_binarize(const float* __restrict__ x) {
    int lane = threadIdx.x & 31;
    int warp = (blockIdx.x * blockDim.x + threadIdx.x) >> 5;
    int pix0 = warp * 8;
#pragma unroll
    for (int i = 0; i < 8; i++) {
        int pix = pix0 + i;
        float v = x[(size_t)pix * CI + lane];
        uint32_t bits = __ballot_sync(0xffffffffu, v >= 0.0f);
        if (lane == 0) g_xbits[pix] = bits;
    }
}

// ---------------------------------------------------------------------------
// K2: binary conv. Block = 256 threads covers a 128-pixel row strip of one
// (batch,row). Thread = (run of 8 pixels) x (pair of couts). Masks live in
// registers (54 regs), x-words in smem (3 rows x 130 words, zero-padded halo).
// ---------------------------------------------------------------------------
__global__ void __launch_bounds__(256) k2_conv(float* __restrict__ y) {
    __shared__ uint32_t sx[3][132];

    int tid = threadIdx.x;
    int x0 = blockIdx.x * 128;
    int yy = blockIdx.y;
    int bz = blockIdx.z;
    const uint32_t* xb = g_xbits + (size_t)bz * (Hh * Ww);

    // Stage 3 rows (y-1..y+1), cols x0-1..x0+128, zero outside the image.
    for (int i = tid; i < 3 * 130; i += 256) {
        int rr = i / 130, cc = i % 130;
        int gy = yy + rr - 1;
        int gx = x0 + cc - 1;
        uint32_t v = 0;
        if (gy >= 0 && gy < Hh && gx >= 0 && gx < Ww) v = xb[gy * Ww + gx];
        sx[rr][cc] = v;
    }
    __syncthreads();

    int g = tid & 15;       // cout pair index
    int r = tid >> 4;       // pixel run index (0..15)
    int pxb = r * 8;
    int co = g * 2;

    // Load this thread's 9 taps x 2 couts x 3 bitplane masks into registers.
    uint32_t mk[9][2][3];
#pragma unroll
    for (int t = 0; t < 9; t++) {
#pragma unroll
        for (int j = 0; j < 2; j++) {
            uint4 v = __ldg(&g_masks[t * CO + co + j]);
            mk[t][j][0] = v.x;
            mk[t][j][1] = v.y;
            mk[t][j][2] = v.z;
        }
    }

    int yc = (yy == 0) ? 0 : ((yy == Hh - 1) ? 2 : 1);
    float* yout = y + (size_t)(bz * Hh + yy) * Ww * CO;

#pragma unroll
    for (int px = 0; px < 8; px++) {
        int col = pxb + px;               // smem col of dx=-1 word
        uint32_t w[9];
#pragma unroll
        for (int rr2 = 0; rr2 < 3; rr2++)
#pragma unroll
            for (int dc = 0; dc < 3; dc++) w[rr2 * 3 + dc] = sx[rr2][col + dc];

        int T = 0;
#pragma unroll
        for (int t = 0; t < 9; t++) T += __popc(w[t]);

        int gx = x0 + col;
        int xc = (gx == 0) ? 0 : ((gx == Ww - 1) ? 2 : 1);
        int cl = yc * 3 + xc;

        float2 outv;
#pragma unroll
        for (int j = 0; j < 2; j++) {
            int A0 = 0, A1 = 0, A2 = 0;
#pragma unroll
            for (int t = 0; t < 9; t++) {
                A0 += __popc(w[t] & mk[t][j][0]);
                A1 += __popc(w[t] & mk[t][j][1]);
                A2 += __popc(w[t] & mk[t][j][2]);
            }
            int val = 4 * (A0 + 2 * A1 + 4 * A2) - 8 * T;
            float bias = __ldg(&g_bias[cl * CO + co + j]);
            ((float*)&outv)[j] = (float)val + bias;
        }
        *(float2*)(yout + (size_t)gx * CO + co) = outv;
    }
}

// ---------------------------------------------------------------------------
extern "C" void kernel_launch(void* const* d_in, const int* in_sizes, int n_in,
                              void* d_out, int out_size) {
    const float* x = (const float*)d_in[0];
    const float* W = (const float*)d_in[1];
    const float* b = (const float*)d_in[2];
    float* y = (float*)d_out;

    k0_prep<<<1, 288>>>(W, b);

    // 16*256*256 = 1,048,576 pixels; 64 pixels per 256-thread block.
    k1_binarize<<<16384, 256>>>(x);

    dim3 grid(Ww / 128, Hh, Bb);
    k2_conv<<<grid, 256>>>(y);
}